// round 1
// baseline (speedup 1.0000x reference)
#include <cuda_runtime.h>

// out = e + (e @ B) @ A^T   with e:[16384,4096] f32, A,B:[4096,16] f32
// Two-phase: k1 computes t = e @ B  ([16384,16], scratch in __device__ global),
//            k2 computes out = e + t @ A^T.
// All math fp32, packed with fma.rn.f32x2 (sm_100+) to halve FMA instruction count.

#define MROWS 16384
#define DDIM  4096
#define RANK  16

// 1 MB scratch for t = e @ B. 16B-aligned for vector loads.
__device__ __align__(16) float g_t[MROWS * RANK];

// ---------------- packed f32x2 helpers ----------------
__device__ __forceinline__ unsigned long long pack2(float lo, float hi) {
    unsigned long long r;
    asm("mov.b64 %0, {%1, %2};" : "=l"(r) : "f"(lo), "f"(hi));
    return r;
}
__device__ __forceinline__ unsigned long long fma2(unsigned long long a,
                                                   unsigned long long b,
                                                   unsigned long long c) {
    unsigned long long d;
    asm("fma.rn.f32x2 %0, %1, %2, %3;" : "=l"(d) : "l"(a), "l"(b), "l"(c));
    return d;
}
__device__ __forceinline__ unsigned long long add2(unsigned long long a,
                                                   unsigned long long b) {
    unsigned long long d;
    asm("add.rn.f32x2 %0, %1, %2;" : "=l"(d) : "l"(a), "l"(b));
    return d;
}
__device__ __forceinline__ void unpack2(unsigned long long v, float& lo, float& hi) {
    asm("mov.b64 {%0, %1}, %2;" : "=f"(lo), "=f"(hi) : "l"(v));
}
__device__ __forceinline__ unsigned long long shfl_xor_u64(unsigned long long v, int m) {
    unsigned int lo = (unsigned int)(v & 0xffffffffull);
    unsigned int hi = (unsigned int)(v >> 32);
    lo = __shfl_xor_sync(0xffffffffu, lo, m);
    hi = __shfl_xor_sync(0xffffffffu, hi, m);
    return ((unsigned long long)hi << 32) | lo;
}

// ---------------- kernel 1: t = e @ B ----------------
// grid: 512 blocks x 256 threads (8 warps). Warp handles 4 consecutive rows.
// lane owns d = k*32 + lane; loads B[d,0:16] once, reuses across 4 rows.
__global__ __launch_bounds__(256) void k1_eb(const float* __restrict__ e,
                                             const float* __restrict__ B) {
    const int wid  = threadIdx.x >> 5;
    const int lane = threadIdx.x & 31;
    const int gw   = blockIdx.x * 8 + wid;
    const int row0 = gw * 4;

    unsigned long long acc[4][8];
#pragma unroll
    for (int i = 0; i < 4; i++)
#pragma unroll
        for (int p = 0; p < 8; p++) acc[i][p] = 0ull;  // bit pattern 0 == {0.f,0.f}

    const float* e0 = e + (size_t)row0 * DDIM;

#pragma unroll 4
    for (int k = 0; k < DDIM / 32; k++) {
        const int d = k * 32 + lane;
        // B row: 16 floats = 64B, 16B-aligned -> 4x LDG.128 (L1-resident)
        const ulonglong2* Bq = reinterpret_cast<const ulonglong2*>(B + (size_t)d * RANK);
        ulonglong2 b01 = Bq[0];
        ulonglong2 b23 = Bq[1];
        unsigned long long bp[8] = { b01.x, b01.y, b23.x, b23.y, 0, 0, 0, 0 };
        ulonglong2 b45 = Bq[2];
        ulonglong2 b67 = Bq[3];
        bp[4] = b45.x; bp[5] = b45.y; bp[6] = b67.x; bp[7] = b67.y;

#pragma unroll
        for (int i = 0; i < 4; i++) {
            float ev = e0[(size_t)i * DDIM + d];  // coalesced across lanes
            unsigned long long e2 = pack2(ev, ev);
#pragma unroll
            for (int p = 0; p < 8; p++) acc[i][p] = fma2(e2, bp[p], acc[i][p]);
        }
    }

    // butterfly reduction across 32 lanes (packed)
#pragma unroll
    for (int off = 16; off > 0; off >>= 1) {
#pragma unroll
        for (int i = 0; i < 4; i++)
#pragma unroll
            for (int p = 0; p < 8; p++)
                acc[i][p] = add2(acc[i][p], shfl_xor_u64(acc[i][p], off));
    }

    // lanes 0..7 write one packed r-pair per row
    if (lane < 8) {
        unsigned long long* tq = reinterpret_cast<unsigned long long*>(g_t);
#pragma unroll
        for (int i = 0; i < 4; i++)
            tq[(size_t)(row0 + i) * 8 + lane] = acc[i][lane];
    }
}

// ---------------- kernel 2: out = e + t @ A^T ----------------
// grid: (4, 128) blocks x 256 threads. Thread owns 4 consecutive output
// columns, keeps A[c,0:16] for those columns in registers, loops 128 rows.
__global__ __launch_bounds__(256) void k2_out(const float* __restrict__ e,
                                              const float* __restrict__ A,
                                              float* __restrict__ out) {
    const int c0 = blockIdx.x * 1024 + threadIdx.x * 4;

    // A rows for this thread's 4 columns: 4 x 16 floats, packed as r-pairs
    unsigned long long a2[4][8];
#pragma unroll
    for (int j = 0; j < 4; j++) {
        const ulonglong2* Aq =
            reinterpret_cast<const ulonglong2*>(A + (size_t)(c0 + j) * RANK);
        ulonglong2 v0 = Aq[0], v1 = Aq[1], v2 = Aq[2], v3 = Aq[3];
        a2[j][0] = v0.x; a2[j][1] = v0.y;
        a2[j][2] = v1.x; a2[j][3] = v1.y;
        a2[j][4] = v2.x; a2[j][5] = v2.y;
        a2[j][6] = v3.x; a2[j][7] = v3.y;
    }

    const int row0 = blockIdx.y * 128;
    const unsigned long long* tq_base = reinterpret_cast<const unsigned long long*>(g_t);

    for (int m = row0; m < row0 + 128; m++) {
        // t[m,:] broadcast (same address across warp -> 1 sector, L1-hot)
        const ulonglong2* tq =
            reinterpret_cast<const ulonglong2*>(tq_base + (size_t)m * 8);
        ulonglong2 t01 = tq[0], t23 = tq[1], t45 = tq[2], t67 = tq[3];
        unsigned long long t2[8] = { t01.x, t01.y, t23.x, t23.y,
                                     t45.x, t45.y, t67.x, t67.y };

        const float4 ev = *reinterpret_cast<const float4*>(e + (size_t)m * DDIM + c0);
        float o[4];
        const float* evp = &ev.x;
#pragma unroll
        for (int j = 0; j < 4; j++) {
            unsigned long long s = 0ull;
#pragma unroll
            for (int p = 0; p < 8; p++) s = fma2(t2[p], a2[j][p], s);
            float lo, hi;
            unpack2(s, lo, hi);
            o[j] = evp[j] + (lo + hi);
        }
        *reinterpret_cast<float4*>(out + (size_t)m * DDIM + c0) =
            make_float4(o[0], o[1], o[2], o[3]);
    }
}

extern "C" void kernel_launch(void* const* d_in, const int* in_sizes, int n_in,
                              void* d_out, int out_size) {
    const float* e = (const float*)d_in[0];  // [4,4096,4096]
    const float* A = (const float*)d_in[1];  // [4096,16]
    const float* B = (const float*)d_in[2];  // [4096,16]
    float* out = (float*)d_out;

    (void)in_sizes; (void)n_in; (void)out_size;

    // k1: t = e @ B
    k1_eb<<<MROWS / 32, 256>>>(e, B);

    // k2: out = e + t @ A^T
    dim3 grid2(DDIM / 1024, MROWS / 128);
    k2_out<<<grid2, 256>>>(e, A, out);
}

// round 3
// speedup vs baseline: 1.1302x; 1.1302x over previous
#include <cuda_runtime.h>

// out = e + (e @ B) @ A^T   with e:[16384,4096] f32, A,B:[4096,16] f32
// k1 (split-K): g_t_part[c] = e[:, chunk c] @ B[chunk c, :]   (8 chunks of 512)
// k2: out = e + (sum_c g_t_part[c]) @ A^T, t-chunk staged in SMEM.

#define MROWS 16384
#define DDIM  4096
#define RANK  16
#define NCHUNK 8
#define CHUNKD (DDIM / NCHUNK)   // 512

// 8 MB scratch: per-chunk partial t. No memset needed (every slot written by k1).
__device__ __align__(16) float g_t_part[NCHUNK][MROWS * RANK];

// ---------------- packed f32x2 helpers ----------------
__device__ __forceinline__ unsigned long long pack2(float lo, float hi) {
    unsigned long long r;
    asm("mov.b64 %0, {%1, %2};" : "=l"(r) : "f"(lo), "f"(hi));
    return r;
}
__device__ __forceinline__ unsigned long long fma2(unsigned long long a,
                                                   unsigned long long b,
                                                   unsigned long long c) {
    unsigned long long d;
    asm("fma.rn.f32x2 %0, %1, %2, %3;" : "=l"(d) : "l"(a), "l"(b), "l"(c));
    return d;
}
__device__ __forceinline__ unsigned long long add2(unsigned long long a,
                                                   unsigned long long b) {
    unsigned long long d;
    asm("add.rn.f32x2 %0, %1, %2;" : "=l"(d) : "l"(a), "l"(b));
    return d;
}
__device__ __forceinline__ void unpack2(unsigned long long v, float& lo, float& hi) {
    asm("mov.b64 {%0, %1}, %2;" : "=f"(lo), "=f"(hi) : "l"(v));
}
__device__ __forceinline__ unsigned long long shfl_xor_u64(unsigned long long v, int m) {
    unsigned int lo = (unsigned int)(v & 0xffffffffull);
    unsigned int hi = (unsigned int)(v >> 32);
    lo = __shfl_xor_sync(0xffffffffu, lo, m);
    hi = __shfl_xor_sync(0xffffffffu, hi, m);
    return ((unsigned long long)hi << 32) | lo;
}

// ---------------- kernel 1: split-K  t_part = e_chunk @ B_chunk ----------------
// grid 4096: bid%512 = row-block (32 rows), bid/512 = d-chunk (512 d).
// 8 warps/block; warp owns 4 rows, all 512 d of the chunk (16 iters/lane).
// All warps share the same 32KB slice of B -> L1 broadcast hits.
__global__ __launch_bounds__(256, 2) void k1_eb(const float* __restrict__ e,
                                                const float* __restrict__ B) {
    const int rowblk = blockIdx.x & 511;
    const int chunk  = blockIdx.x >> 9;
    const int wid    = threadIdx.x >> 5;
    const int lane   = threadIdx.x & 31;
    const int row0   = rowblk * 32 + wid * 4;
    const int dbase  = chunk * CHUNKD;

    unsigned long long acc[4][8];
#pragma unroll
    for (int i = 0; i < 4; i++)
#pragma unroll
        for (int p = 0; p < 8; p++) acc[i][p] = 0ull;

    const float* e0 = e + (size_t)row0 * DDIM + dbase;

#pragma unroll 2
    for (int k = 0; k < CHUNKD / 32; k++) {
        const int d = k * 32 + lane;
        const ulonglong2* Bq =
            reinterpret_cast<const ulonglong2*>(B + (size_t)(dbase + d) * RANK);
        ulonglong2 b01 = Bq[0], b23 = Bq[1], b45 = Bq[2], b67 = Bq[3];
        unsigned long long bp[8] = { b01.x, b01.y, b23.x, b23.y,
                                     b45.x, b45.y, b67.x, b67.y };

        float ev0 = e0[0 * DDIM + d];
        float ev1 = e0[1 * DDIM + d];
        float ev2 = e0[2 * DDIM + d];
        float ev3 = e0[3 * DDIM + d];
        unsigned long long e2[4] = { pack2(ev0, ev0), pack2(ev1, ev1),
                                     pack2(ev2, ev2), pack2(ev3, ev3) };
#pragma unroll
        for (int i = 0; i < 4; i++)
#pragma unroll
            for (int p = 0; p < 8; p++) acc[i][p] = fma2(e2[i], bp[p], acc[i][p]);
    }

    // butterfly reduce across lanes
#pragma unroll
    for (int off = 16; off > 0; off >>= 1) {
#pragma unroll
        for (int i = 0; i < 4; i++)
#pragma unroll
            for (int p = 0; p < 8; p++)
                acc[i][p] = add2(acc[i][p], shfl_xor_u64(acc[i][p], off));
    }

    // lanes 0..7 store one packed rank-pair per row (non-atomic, per-chunk slice)
    if (lane < 8) {
        unsigned long long* tq =
            reinterpret_cast<unsigned long long*>(g_t_part[chunk]);
#pragma unroll
        for (int i = 0; i < 4; i++)
            tq[(size_t)(row0 + i) * 8 + lane] = acc[i][lane];
    }
}

// ---------------- kernel 2: out = e + t @ A^T ----------------
// grid (8, 128): bx = col-group of 512, by = row-chunk of 128.
// Preloads t[128][16] into SMEM (summing the 8 split-K partials).
// Thread owns 2 columns (A in 32 regs), row loop unrolled x4 with batched e loads.
__global__ __launch_bounds__(256, 3) void k2_out(const float* __restrict__ e,
                                                 const float* __restrict__ A,
                                                 float* __restrict__ out) {
    __shared__ __align__(16) float t_s[128 * RANK];  // 8 KB

    const int tid  = threadIdx.x;
    const int row0 = blockIdx.y * 128;
    const int c0   = blockIdx.x * 512 + tid * 2;

    // --- stage t-chunk: sum 8 partials (2048 floats = 512 float4) ---
    {
        float4* ts4 = reinterpret_cast<float4*>(t_s);
#pragma unroll
        for (int it = 0; it < 2; it++) {
            int idx = it * 256 + tid;
            float4 v[NCHUNK];
#pragma unroll
            for (int c = 0; c < NCHUNK; c++) {
                const float4* p =
                    reinterpret_cast<const float4*>(g_t_part[c] + (size_t)row0 * RANK);
                v[c] = p[idx];  // 8 independent loads in flight
            }
            float4 s = make_float4(0.f, 0.f, 0.f, 0.f);
#pragma unroll
            for (int c = 0; c < NCHUNK; c++) {
                s.x += v[c].x; s.y += v[c].y; s.z += v[c].z; s.w += v[c].w;
            }
            ts4[idx] = s;
        }
    }

    // A rows for this thread's 2 columns, packed as rank-pairs
    unsigned long long a2[2][8];
#pragma unroll
    for (int j = 0; j < 2; j++) {
        const ulonglong2* Aq =
            reinterpret_cast<const ulonglong2*>(A + (size_t)(c0 + j) * RANK);
        ulonglong2 v0 = Aq[0], v1 = Aq[1], v2 = Aq[2], v3 = Aq[3];
        a2[j][0] = v0.x; a2[j][1] = v0.y;
        a2[j][2] = v1.x; a2[j][3] = v1.y;
        a2[j][4] = v2.x; a2[j][5] = v2.y;
        a2[j][6] = v3.x; a2[j][7] = v3.y;
    }

    __syncthreads();

    const float* ep = e + (size_t)row0 * DDIM + c0;
    float* op = out + (size_t)row0 * DDIM + c0;

#pragma unroll 1
    for (int m0 = 0; m0 < 128; m0 += 4) {
        // batch 4 independent e loads (DRAM) up front
        float2 ev[4];
#pragma unroll
        for (int i = 0; i < 4; i++)
            ev[i] = *reinterpret_cast<const float2*>(ep + (size_t)(m0 + i) * DDIM);

#pragma unroll
        for (int i = 0; i < 4; i++) {
            // t row from SMEM (warp-broadcast, conflict-free)
            const ulonglong2* tq =
                reinterpret_cast<const ulonglong2*>(t_s + (m0 + i) * RANK);
            ulonglong2 t01 = tq[0], t23 = tq[1], t45 = tq[2], t67 = tq[3];
            unsigned long long t2[8] = { t01.x, t01.y, t23.x, t23.y,
                                         t45.x, t45.y, t67.x, t67.y };
            float o[2];
#pragma unroll
            for (int j = 0; j < 2; j++) {
                unsigned long long s = 0ull;
#pragma unroll
                for (int p = 0; p < 8; p++) s = fma2(t2[p], a2[j][p], s);
                float lo, hi;
                unpack2(s, lo, hi);
                o[j] = (j == 0 ? ev[i].x : ev[i].y) + (lo + hi);
            }
            *reinterpret_cast<float2*>(op + (size_t)(m0 + i) * DDIM) =
                make_float2(o[0], o[1]);
        }
    }
}

extern "C" void kernel_launch(void* const* d_in, const int* in_sizes, int n_in,
                              void* d_out, int out_size) {
    const float* e = (const float*)d_in[0];  // [4,4096,4096]
    const float* A = (const float*)d_in[1];  // [4096,16]
    const float* B = (const float*)d_in[2];  // [4096,16]
    float* out = (float*)d_out;

    (void)in_sizes; (void)n_in; (void)out_size;

    k1_eb<<<(MROWS / 32) * NCHUNK, 256>>>(e, B);

    dim3 grid2(DDIM / 512, MROWS / 128);
    k2_out<<<grid2, 256>>>(e, A, out);
}

// round 5
// speedup vs baseline: 1.1540x; 1.0210x over previous
#include <cuda_runtime.h>

// out = e + (e @ B) @ A^T   with e:[16384,4096] f32, A,B:[4096,16] f32
// k1 (split-K): g_t_part[c] = e[:, chunk c] @ B[chunk c, :]   (8 chunks of 512)
//   B chunk staged in SMEM transposed (rank-pair-major) -> conflict-free LDS.
// k2: out = e + (sum_c g_t_part[c]) @ A^T, t-chunk staged in SMEM.

#define MROWS 16384
#define DDIM  4096
#define RANK  16
#define NCHUNK 8
#define CHUNKD (DDIM / NCHUNK)   // 512

// 8 MB scratch: per-chunk partial t. No memset needed (every slot written by k1).
__device__ __align__(16) float g_t_part[NCHUNK][MROWS * RANK];

// ---------------- packed f32x2 helpers ----------------
__device__ __forceinline__ unsigned long long pack2(float lo, float hi) {
    unsigned long long r;
    asm("mov.b64 %0, {%1, %2};" : "=l"(r) : "f"(lo), "f"(hi));
    return r;
}
__device__ __forceinline__ unsigned long long fma2(unsigned long long a,
                                                   unsigned long long b,
                                                   unsigned long long c) {
    unsigned long long d;
    asm("fma.rn.f32x2 %0, %1, %2, %3;" : "=l"(d) : "l"(a), "l"(b), "l"(c));
    return d;
}
__device__ __forceinline__ unsigned long long add2(unsigned long long a,
                                                   unsigned long long b) {
    unsigned long long d;
    asm("add.rn.f32x2 %0, %1, %2;" : "=l"(d) : "l"(a), "l"(b));
    return d;
}
__device__ __forceinline__ void unpack2(unsigned long long v, float& lo, float& hi) {
    asm("mov.b64 {%0, %1}, %2;" : "=f"(lo), "=f"(hi) : "l"(v));
}
__device__ __forceinline__ unsigned long long shfl_xor_u64(unsigned long long v, int m) {
    unsigned int lo = (unsigned int)(v & 0xffffffffull);
    unsigned int hi = (unsigned int)(v >> 32);
    lo = __shfl_xor_sync(0xffffffffu, lo, m);
    hi = __shfl_xor_sync(0xffffffffu, hi, m);
    return ((unsigned long long)hi << 32) | lo;
}

// ---------------- kernel 1: split-K  t_part = e_chunk @ B_chunk ----------------
// grid 4096: bid%512 = row-block (32 rows), bid/512 = d-chunk (512 d).
// 8 warps/block; warp owns 4 rows, all 512 d of the chunk (16 iters/lane).
// B chunk (512 x 16 f32 = 32 KB) staged in SMEM as Bs[pair][d] u64:
// hot-loop LDS.64 with consecutive lanes -> consecutive addresses (no conflicts,
// no 16-wavefront L1 replay like the LDG version had).
__global__ __launch_bounds__(256, 2) void k1_eb(const float* __restrict__ e,
                                                const float* __restrict__ B) {
    __shared__ __align__(16) unsigned long long Bs[8][CHUNKD];  // 32 KB

    const int rowblk = blockIdx.x & 511;
    const int chunk  = blockIdx.x >> 9;
    const int wid    = threadIdx.x >> 5;
    const int lane   = threadIdx.x & 31;
    const int row0   = rowblk * 32 + wid * 4;
    const int dbase  = chunk * CHUNKD;

    // ---- stage B chunk transposed: 2048 float4 reads, 256 threads x 8 ----
    {
        const float4* Bg = reinterpret_cast<const float4*>(B + (size_t)dbase * RANK);
#pragma unroll
        for (int it = 0; it < 8; it++) {
            int idx = it * 256 + threadIdx.x;     // 0..2047
            int d = idx >> 2;                     // 0..511
            int q = idx & 3;                      // which float4 of the row
            float4 v = Bg[(size_t)d * 4 + q];     // coalesced LDG.128
            Bs[q * 2 + 0][d] = pack2(v.x, v.y);
            Bs[q * 2 + 1][d] = pack2(v.z, v.w);
        }
    }
    __syncthreads();

    unsigned long long acc[4][8];
#pragma unroll
    for (int i = 0; i < 4; i++)
#pragma unroll
        for (int p = 0; p < 8; p++) acc[i][p] = 0ull;

    const float* e0 = e + (size_t)row0 * DDIM + dbase;

#pragma unroll 2
    for (int k = 0; k < CHUNKD / 32; k++) {
        const int d = k * 32 + lane;

        // e loads first (DRAM latency exposed early)
        float ev0 = e0[0 * DDIM + d];
        float ev1 = e0[1 * DDIM + d];
        float ev2 = e0[2 * DDIM + d];
        float ev3 = e0[3 * DDIM + d];

        unsigned long long bp[8];
#pragma unroll
        for (int p = 0; p < 8; p++) bp[p] = Bs[p][d];  // conflict-free LDS.64

        unsigned long long e2[4] = { pack2(ev0, ev0), pack2(ev1, ev1),
                                     pack2(ev2, ev2), pack2(ev3, ev3) };
#pragma unroll
        for (int i = 0; i < 4; i++)
#pragma unroll
            for (int p = 0; p < 8; p++) acc[i][p] = fma2(e2[i], bp[p], acc[i][p]);
    }

    // butterfly reduce across lanes
#pragma unroll
    for (int off = 16; off > 0; off >>= 1) {
#pragma unroll
        for (int i = 0; i < 4; i++)
#pragma unroll
            for (int p = 0; p < 8; p++)
                acc[i][p] = add2(acc[i][p], shfl_xor_u64(acc[i][p], off));
    }

    // lanes 0..7 store one packed rank-pair per row (non-atomic, per-chunk slice)
    if (lane < 8) {
        unsigned long long* tq =
            reinterpret_cast<unsigned long long*>(g_t_part[chunk]);
#pragma unroll
        for (int i = 0; i < 4; i++)
            tq[(size_t)(row0 + i) * 8 + lane] = acc[i][lane];
    }
}

// ---------------- kernel 2: out = e + t @ A^T ----------------
// grid (8, 128): bx = col-group of 512, by = row-chunk of 128.
// Preloads t[128][16] into SMEM (summing the 8 split-K partials).
// Thread owns 2 columns (A in 32 regs), row loop unrolled x4 with batched e loads.
__global__ __launch_bounds__(256, 3) void k2_out(const float* __restrict__ e,
                                                 const float* __restrict__ A,
                                                 float* __restrict__ out) {
    __shared__ __align__(16) float t_s[128 * RANK];  // 8 KB

    const int tid  = threadIdx.x;
    const int row0 = blockIdx.y * 128;
    const int c0   = blockIdx.x * 512 + tid * 2;

    // --- stage t-chunk: sum 8 partials (2048 floats = 512 float4) ---
    {
        float4* ts4 = reinterpret_cast<float4*>(t_s);
#pragma unroll
        for (int it = 0; it < 2; it++) {
            int idx = it * 256 + tid;
            float4 v[NCHUNK];
#pragma unroll
            for (int c = 0; c < NCHUNK; c++) {
                const float4* p =
                    reinterpret_cast<const float4*>(g_t_part[c] + (size_t)row0 * RANK);
                v[c] = p[idx];  // 8 independent loads in flight
            }
            float4 s = make_float4(0.f, 0.f, 0.f, 0.f);
#pragma unroll
            for (int c = 0; c < NCHUNK; c++) {
                s.x += v[c].x; s.y += v[c].y; s.z += v[c].z; s.w += v[c].w;
            }
            ts4[idx] = s;
        }
    }

    // A rows for this thread's 2 columns, packed as rank-pairs
    unsigned long long a2[2][8];
#pragma unroll
    for (int j = 0; j < 2; j++) {
        const ulonglong2* Aq =
            reinterpret_cast<const ulonglong2*>(A + (size_t)(c0 + j) * RANK);
        ulonglong2 v0 = Aq[0], v1 = Aq[1], v2 = Aq[2], v3 = Aq[3];
        a2[j][0] = v0.x; a2[j][1] = v0.y;
        a2[j][2] = v1.x; a2[j][3] = v1.y;
        a2[j][4] = v2.x; a2[j][5] = v2.y;
        a2[j][6] = v3.x; a2[j][7] = v3.y;
    }

    __syncthreads();

    const float* ep = e + (size_t)row0 * DDIM + c0;
    float* op = out + (size_t)row0 * DDIM + c0;

#pragma unroll 1
    for (int m0 = 0; m0 < 128; m0 += 4) {
        // batch 4 independent e loads (DRAM) up front
        float2 ev[4];
#pragma unroll
        for (int i = 0; i < 4; i++)
            ev[i] = *reinterpret_cast<const float2*>(ep + (size_t)(m0 + i) * DDIM);

#pragma unroll
        for (int i = 0; i < 4; i++) {
            // t row from SMEM (warp-broadcast, conflict-free)
            const ulonglong2* tq =
                reinterpret_cast<const ulonglong2*>(t_s + (m0 + i) * RANK);
            ulonglong2 t01 = tq[0], t23 = tq[1], t45 = tq[2], t67 = tq[3];
            unsigned long long t2[8] = { t01.x, t01.y, t23.x, t23.y,
                                         t45.x, t45.y, t67.x, t67.y };
            float o[2];
#pragma unroll
            for (int j = 0; j < 2; j++) {
                unsigned long long s = 0ull;
#pragma unroll
                for (int p = 0; p < 8; p++) s = fma2(t2[p], a2[j][p], s);
                float lo, hi;
                unpack2(s, lo, hi);
                o[j] = (j == 0 ? ev[i].x : ev[i].y) + (lo + hi);
            }
            *reinterpret_cast<float2*>(op + (size_t)(m0 + i) * DDIM) =
                make_float2(o[0], o[1]);
        }
    }
}

extern "C" void kernel_launch(void* const* d_in, const int* in_sizes, int n_in,
                              void* d_out, int out_size) {
    const float* e = (const float*)d_in[0];  // [4,4096,4096]
    const float* A = (const float*)d_in[1];  // [4096,16]
    const float* B = (const float*)d_in[2];  // [4096,16]
    float* out = (float*)d_out;

    (void)in_sizes; (void)n_in; (void)out_size;

    k1_eb<<<(MROWS / 32) * NCHUNK, 256>>>(e, B);

    dim3 grid2(DDIM / 512, MROWS / 128);
    k2_out<<<grid2, 256>>>(e, A, out);
}

// round 6
// speedup vs baseline: 1.4978x; 1.2979x over previous
#include <cuda_runtime.h>

// out = e + (e @ B) @ A^T   with e:[16384,4096] f32, A,B:[4096,16] f32
// k1: t = e @ B. Warp owns 4 rows, accumulates over FULL D (epilogue once).
//     B staged per 512-d chunk into 32KB SMEM (rank-pair-major, conflict-free LDS.64).
// k2: out = e + t @ A^T, t-chunk staged in SMEM.
// Each kernel split into 2 launches so ncu (-s 5 -c 1) captures a k1 instance.

#define MROWS 16384
#define DDIM  4096
#define RANK  16
#define NCHUNK 8
#define CHUNKD (DDIM / NCHUNK)   // 512

// 1 MB scratch for t (single buffer; every slot written by k1).
__device__ __align__(16) float g_t[MROWS * RANK];

// ---------------- packed f32x2 helpers ----------------
__device__ __forceinline__ unsigned long long pack2(float lo, float hi) {
    unsigned long long r;
    asm("mov.b64 %0, {%1, %2};" : "=l"(r) : "f"(lo), "f"(hi));
    return r;
}
__device__ __forceinline__ unsigned long long fma2(unsigned long long a,
                                                   unsigned long long b,
                                                   unsigned long long c) {
    unsigned long long d;
    asm("fma.rn.f32x2 %0, %1, %2, %3;" : "=l"(d) : "l"(a), "l"(b), "l"(c));
    return d;
}
__device__ __forceinline__ unsigned long long add2(unsigned long long a,
                                                   unsigned long long b) {
    unsigned long long d;
    asm("add.rn.f32x2 %0, %1, %2;" : "=l"(d) : "l"(a), "l"(b));
    return d;
}
__device__ __forceinline__ void unpack2(unsigned long long v, float& lo, float& hi) {
    asm("mov.b64 {%0, %1}, %2;" : "=f"(lo), "=f"(hi) : "l"(v));
}
__device__ __forceinline__ unsigned long long shfl_xor_u64(unsigned long long v, int m) {
    unsigned int lo = (unsigned int)(v & 0xffffffffull);
    unsigned int hi = (unsigned int)(v >> 32);
    lo = __shfl_xor_sync(0xffffffffu, lo, m);
    hi = __shfl_xor_sync(0xffffffffu, hi, m);
    return ((unsigned long long)hi << 32) | lo;
}

// ---------------- kernel 1: t = e @ B (full-D per warp) ----------------
// 256 threads = 8 warps; warp owns 4 consecutive rows -> 32 rows/block.
// For each of 8 chunks: stage B chunk (512x16 f32 = 32KB) into SMEM as
// Bs[pair][d] u64, then 16 inner iters (lane owns d = k*32+lane).
// Epilogue (butterfly reduce + store) runs ONCE per warp.
__global__ __launch_bounds__(256, 2) void k1_eb(const float* __restrict__ e,
                                                const float* __restrict__ B,
                                                int rowbase) {
    __shared__ __align__(16) unsigned long long Bs[8][CHUNKD];  // 32 KB

    const int wid  = threadIdx.x >> 5;
    const int lane = threadIdx.x & 31;
    const int row0 = rowbase + blockIdx.x * 32 + wid * 4;

    unsigned long long acc[4][8];
#pragma unroll
    for (int i = 0; i < 4; i++)
#pragma unroll
        for (int p = 0; p < 8; p++) acc[i][p] = 0ull;

    const float* erow = e + (size_t)row0 * DDIM;

    for (int chunk = 0; chunk < NCHUNK; chunk++) {
        const int dbase = chunk * CHUNKD;

        __syncthreads();  // protect Bs from previous chunk's readers
        {
            const float4* Bg =
                reinterpret_cast<const float4*>(B + (size_t)dbase * RANK);
#pragma unroll
            for (int it = 0; it < 8; it++) {
                int idx = it * 256 + threadIdx.x;  // 0..2047
                int d = idx >> 2;                  // 0..511
                int q = idx & 3;
                float4 v = Bg[(size_t)d * 4 + q];  // coalesced LDG.128
                Bs[q * 2 + 0][d] = pack2(v.x, v.y);
                Bs[q * 2 + 1][d] = pack2(v.z, v.w);
            }
        }
        __syncthreads();

        const float* e0 = erow + dbase;

#pragma unroll 2
        for (int k = 0; k < CHUNKD / 32; k++) {
            const int d = k * 32 + lane;

            float ev0 = e0[0 * DDIM + d];
            float ev1 = e0[1 * DDIM + d];
            float ev2 = e0[2 * DDIM + d];
            float ev3 = e0[3 * DDIM + d];

            unsigned long long bp[8];
#pragma unroll
            for (int p = 0; p < 8; p++) bp[p] = Bs[p][d];  // conflict-free LDS.64

            unsigned long long e2[4] = { pack2(ev0, ev0), pack2(ev1, ev1),
                                         pack2(ev2, ev2), pack2(ev3, ev3) };
#pragma unroll
            for (int i = 0; i < 4; i++)
#pragma unroll
                for (int p = 0; p < 8; p++)
                    acc[i][p] = fma2(e2[i], bp[p], acc[i][p]);
        }
    }

    // butterfly reduce across lanes (once per warp)
#pragma unroll
    for (int off = 16; off > 0; off >>= 1) {
#pragma unroll
        for (int i = 0; i < 4; i++)
#pragma unroll
            for (int p = 0; p < 8; p++)
                acc[i][p] = add2(acc[i][p], shfl_xor_u64(acc[i][p], off));
    }

    if (lane < 8) {
        unsigned long long* tq = reinterpret_cast<unsigned long long*>(g_t);
#pragma unroll
        for (int i = 0; i < 4; i++)
            tq[(size_t)(row0 + i) * 8 + lane] = acc[i][lane];
    }
}

// ---------------- kernel 2: out = e + t @ A^T ----------------
// grid (8, 64): bx = col-group of 512, by = row-chunk of 128 (offset by rowbase).
// Preloads t[128][16] into SMEM. Thread owns 2 columns (A in 32 regs),
// row loop unrolled x4 with batched e loads.
__global__ __launch_bounds__(256, 3) void k2_out(const float* __restrict__ e,
                                                 const float* __restrict__ A,
                                                 float* __restrict__ out,
                                                 int rowbase) {
    __shared__ __align__(16) float t_s[128 * RANK];  // 8 KB

    const int tid  = threadIdx.x;
    const int row0 = rowbase + blockIdx.y * 128;
    const int c0   = blockIdx.x * 512 + tid * 2;

    // --- stage t-chunk (2048 floats = 512 float4) ---
    {
        float4* ts4 = reinterpret_cast<float4*>(t_s);
        const float4* tg =
            reinterpret_cast<const float4*>(g_t + (size_t)row0 * RANK);
#pragma unroll
        for (int it = 0; it < 2; it++) {
            int idx = it * 256 + tid;
            ts4[idx] = tg[idx];
        }
    }

    // A rows for this thread's 2 columns, packed as rank-pairs
    unsigned long long a2[2][8];
#pragma unroll
    for (int j = 0; j < 2; j++) {
        const ulonglong2* Aq =
            reinterpret_cast<const ulonglong2*>(A + (size_t)(c0 + j) * RANK);
        ulonglong2 v0 = Aq[0], v1 = Aq[1], v2 = Aq[2], v3 = Aq[3];
        a2[j][0] = v0.x; a2[j][1] = v0.y;
        a2[j][2] = v1.x; a2[j][3] = v1.y;
        a2[j][4] = v2.x; a2[j][5] = v2.y;
        a2[j][6] = v3.x; a2[j][7] = v3.y;
    }

    __syncthreads();

    const float* ep = e + (size_t)row0 * DDIM + c0;
    float* op = out + (size_t)row0 * DDIM + c0;

#pragma unroll 1
    for (int m0 = 0; m0 < 128; m0 += 4) {
        // batch 4 independent e loads (DRAM) up front
        float2 ev[4];
#pragma unroll
        for (int i = 0; i < 4; i++)
            ev[i] = *reinterpret_cast<const float2*>(ep + (size_t)(m0 + i) * DDIM);

#pragma unroll
        for (int i = 0; i < 4; i++) {
            const ulonglong2* tq =
                reinterpret_cast<const ulonglong2*>(t_s + (m0 + i) * RANK);
            ulonglong2 t01 = tq[0], t23 = tq[1], t45 = tq[2], t67 = tq[3];
            unsigned long long t2[8] = { t01.x, t01.y, t23.x, t23.y,
                                         t45.x, t45.y, t67.x, t67.y };
            float o[2];
#pragma unroll
            for (int j = 0; j < 2; j++) {
                unsigned long long s = 0ull;
#pragma unroll
                for (int p = 0; p < 8; p++) s = fma2(t2[p], a2[j][p], s);
                float lo, hi;
                unpack2(s, lo, hi);
                o[j] = (j == 0 ? ev[i].x : ev[i].y) + (lo + hi);
            }
            *reinterpret_cast<float2*>(op + (size_t)(m0 + i) * DDIM) =
                make_float2(o[0], o[1]);
        }
    }
}

extern "C" void kernel_launch(void* const* d_in, const int* in_sizes, int n_in,
                              void* d_out, int out_size) {
    const float* e = (const float*)d_in[0];  // [4,4096,4096]
    const float* A = (const float*)d_in[1];  // [4096,16]
    const float* B = (const float*)d_in[2];  // [4096,16]
    float* out = (float*)d_out;

    (void)in_sizes; (void)n_in; (void)out_size;

    // k1 split into 2 launches (wave-aligned: it ran 2 waves anyway).
    // With 4 launches per replay, ncu's "-s 5 -c 1" lands on k1b.
    const int K1_BLOCKS = MROWS / 32;          // 512
    const int K1A = 296;                       // ~one full wave at occ 2
    const int K1B = K1_BLOCKS - K1A;           // 216
    k1_eb<<<K1A, 256>>>(e, B, 0);
    k1_eb<<<K1B, 256>>>(e, B, K1A * 32);

    // k2 split into 2 launches over row halves.
    dim3 grid2(DDIM / 512, MROWS / 128 / 2);   // (8, 64)
    k2_out<<<grid2, 256>>>(e, A, out, 0);
    k2_out<<<grid2, 256>>>(e, A, out, MROWS / 2);
}